// round 1
// baseline (speedup 1.0000x reference)
#include <cuda_runtime.h>
#include <cuda_bf16.h>

// DeltaNet chunkwise delta-rule linear attention with decay.
// b=4 h=4 (BH=16), L=4096, dk=dv=256, chunk C=32, NCH=128 chunks.
//
// Structure:
//  pre_kernel  : per-chunk parallel precompute (norms, T via forward subst, u_raw, w, attn, gamma-mean)
//  zero_kernel : S0 = 0
//  scan_kernel : 128 sequential launches, each advances all 16 (b,h) states one chunk.
//                grid (8 vblocks x 16 bh) = 128 CTAs, 256 threads, 144KB dynamic smem.

#define BHn 16
#define LSEQ 4096
#define DK 256
#define DV 256
#define CC 32
#define NCH 128
#define CHELEM (CC*DK)          // 8192 floats per chunk per tensor

// -------- scratch (device globals; no allocation allowed) --------
__device__ float g_qT[BHn*NCH*CHELEM];     // [bh][ch][k][c]  (k-major, 64MB)
__device__ float g_kn[BHn*NCH*CHELEM];     // [bh][ch][c][k]  (c-major)
__device__ float g_wT[BHn*NCH*CHELEM];     // [bh][ch][k][c]
__device__ float g_u [BHn*NCH*CHELEM];     // [bh][ch][c][v]  (u_raw)
__device__ float g_attnT[BHn*NCH*CC*CC];   // [bh][ch][d][c] = attn[c][d] (masked d<=c)
__device__ float g_gm[BHn*NCH];
__device__ float g_S[2][BHn*DK*DV];        // ping-pong state

// ================= preprocess =================
// smem: qs[32][260], ks[32][260], As[32][33], beta[32], gamma[32]
#define PRE_SMEM_FLOATS (8320+8320+1056+32+32)

__global__ void pre_kernel(const float* __restrict__ q, const float* __restrict__ k,
                           const float* __restrict__ v, const float* __restrict__ beta,
                           const float* __restrict__ gamma) {
    extern __shared__ float sm[];
    float* qs = sm;              // 32*260
    float* ks = sm + 8320;       // 32*260
    float* As = sm + 16640;      // 32*33
    float* bs = sm + 17696;      // 32
    float* gs = sm + 17728;      // 32

    const int tid  = threadIdx.x;
    const int lane = tid & 31;
    const int wid  = tid >> 5;
    const int bh = blockIdx.x >> 7;
    const int ch = blockIdx.x & 127;
    const long tok0 = (long)bh*LSEQ + (long)ch*CC;

    const float* qg = q + tok0*DK;
    const float* kg = k + tok0*DK;

    // ---- load q,k chunk (coalesced; thread = column) ----
    #pragma unroll 8
    for (int i = 0; i < 32; i++) {
        qs[i*260 + tid] = qg[i*DK + tid];
        ks[i*260 + tid] = kg[i*DK + tid];
    }
    if (tid < 32) { bs[tid] = beta[tok0 + tid]; gs[tid] = gamma[tok0 + tid]; }
    __syncthreads();

    // ---- l2 normalize rows (warp per row) ----
    for (int r = wid; r < 32; r += 8) {
        float s = 0.f;
        #pragma unroll
        for (int x = lane; x < 256; x += 32) { float t = qs[r*260+x]; s += t*t; }
        s += __shfl_xor_sync(0xffffffffu, s, 16);
        s += __shfl_xor_sync(0xffffffffu, s, 8);
        s += __shfl_xor_sync(0xffffffffu, s, 4);
        s += __shfl_xor_sync(0xffffffffu, s, 2);
        s += __shfl_xor_sync(0xffffffffu, s, 1);
        float inv = rsqrtf(s + 1e-6f);
        #pragma unroll
        for (int x = lane; x < 256; x += 32) qs[r*260+x] *= inv;

        float s2 = 0.f;
        #pragma unroll
        for (int x = lane; x < 256; x += 32) { float t = ks[r*260+x]; s2 += t*t; }
        s2 += __shfl_xor_sync(0xffffffffu, s2, 16);
        s2 += __shfl_xor_sync(0xffffffffu, s2, 8);
        s2 += __shfl_xor_sync(0xffffffffu, s2, 4);
        s2 += __shfl_xor_sync(0xffffffffu, s2, 2);
        s2 += __shfl_xor_sync(0xffffffffu, s2, 1);
        float inv2 = rsqrtf(s2 + 1e-6f);
        #pragma unroll
        for (int x = lane; x < 256; x += 32) ks[r*260+x] *= inv2;
    }
    __syncthreads();

    const long cb = ((long)bh*NCH + ch)*CHELEM;

    // ---- write kn (c-major, coalesced) and qT (k-major) ----
    {
        float* knp = g_kn + cb;
        #pragma unroll 8
        for (int i = 0; i < 32; i++) knp[i*DK + tid] = ks[i*260 + tid];
        float* qTp = g_qT + cb;
        #pragma unroll
        for (int g2 = 0; g2 < 8; g2++) {
            float4 t4 = make_float4(qs[(g2*4+0)*260+tid], qs[(g2*4+1)*260+tid],
                                    qs[(g2*4+2)*260+tid], qs[(g2*4+3)*260+tid]);
            *(float4*)&g_qT[cb + (long)tid*32 + g2*4] = t4;
            (void)qTp;
        }
    }

    // ---- A = -beta_i * (kn_i . kn_j), j<i ; attnT[j][i] = (j<=i)? qn_i.kn_j : 0 ----
    {
        float* atp = g_attnT + ((long)bh*NCH + ch)*CC*CC;
        #pragma unroll
        for (int p = 0; p < 4; p++) {
            int j = p*8 + wid;      // constant per warp -> broadcast reads of row j
            int i = lane;
            float accA = 0.f, accQ = 0.f;
            #pragma unroll 8
            for (int k4 = 0; k4 < 64; k4++) {
                float4 kj = *(float4*)&ks[j*260 + k4*4];
                float4 ki = *(float4*)&ks[i*260 + k4*4];
                float4 qi = *(float4*)&qs[i*260 + k4*4];
                accA += ki.x*kj.x + ki.y*kj.y + ki.z*kj.z + ki.w*kj.w;
                accQ += qi.x*kj.x + qi.y*kj.y + qi.z*kj.z + qi.w*kj.w;
            }
            if (j < i) As[i*33 + j] = -bs[i]*accA;
            atp[j*32 + i] = (j <= i) ? accQ : 0.0f;
        }
    }
    __syncthreads();

    // ---- forward substitution (warp 0): T = (I-A)^{-1}, stored as strict-lower in As ----
    if (wid == 0) {
        int col = lane;
        for (int i = 1; i < 32; i++) {
            float inc = 0.f;
            if (col < i) {
                for (int j = col+1; j < i; j++) inc += As[i*33+j]*As[j*33+col];
            }
            __syncwarp();
            if (col < i) As[i*33+col] += inc;
            __syncwarp();
        }
    }
    // ---- gamma mean (warp 1) ----
    if (wid == 1) {
        float g2 = gs[lane];
        g2 += __shfl_xor_sync(0xffffffffu, g2, 16);
        g2 += __shfl_xor_sync(0xffffffffu, g2, 8);
        g2 += __shfl_xor_sync(0xffffffffu, g2, 4);
        g2 += __shfl_xor_sync(0xffffffffu, g2, 2);
        g2 += __shfl_xor_sync(0xffffffffu, g2, 1);
        if (lane == 0) g_gm[bh*NCH + ch] = g2 * (1.0f/32.0f);
    }
    __syncthreads();

    // ---- u_raw = T (beta*v): thread = column v ----
    {
        float colv[32];
        const float* vg = v + tok0*DV;
        #pragma unroll
        for (int j = 0; j < 32; j++) colv[j] = vg[j*DV + tid] * bs[j];
        float* up = g_u + cb;
        #pragma unroll
        for (int i = 0; i < 32; i++) {
            float acc = colv[i];
            #pragma unroll
            for (int j = 0; j < i; j++) acc += As[i*33+j]*colv[j];
            up[i*DV + tid] = acc;
        }
    }
    // ---- w = T (beta*kn): thread = column k, write k-major (wT) ----
    {
        float colk[32];
        #pragma unroll
        for (int j = 0; j < 32; j++) colk[j] = ks[j*260 + tid] * bs[j];
        float wout[32];
        #pragma unroll
        for (int i = 0; i < 32; i++) {
            float acc = colk[i];
            #pragma unroll
            for (int j = 0; j < i; j++) acc += As[i*33+j]*colk[j];
            wout[i] = acc;
        }
        #pragma unroll
        for (int g2 = 0; g2 < 8; g2++)
            *(float4*)&g_wT[cb + (long)tid*32 + g2*4] =
                make_float4(wout[g2*4], wout[g2*4+1], wout[g2*4+2], wout[g2*4+3]);
    }
}

// ================= S0 = 0 =================
__global__ void zero_kernel() {
    int i = blockIdx.x*256 + threadIdx.x;   // grid 4096 -> 1,048,576
    g_S[0][i] = 0.0f;
}

// ================= scan step =================
// smem: Ss[256][36] | wT[256][32] | qT[256][32] | kns[32][256] | aT[32][36] | us[32][36]
#define SCAN_SMEM_FLOATS (9216+8192+8192+8192+1152+1152)

__global__ void scan_kernel(int t, float* __restrict__ outp, float* __restrict__ sFinal) {
    extern __shared__ float sm[];
    float* Ss  = sm;           // 256*36
    float* wT  = sm + 9216;    // 256*32
    float* qT  = sm + 17408;   // 256*32
    float* kns = sm + 25600;   // 32*256
    float* aT  = sm + 33792;   // 32*36
    float* us  = sm + 34944;   // 32*36

    const int tid  = threadIdx.x;
    const int lane = tid & 31;
    const int wid  = tid >> 5;
    const int bh = blockIdx.y;
    const int v0 = blockIdx.x * 32;

    const float* Sin  = g_S[t & 1]     + (long)bh*DK*DV;
    float*       Sout = g_S[(t+1) & 1] + (long)bh*DK*DV;
    const long cb = ((long)bh*NCH + t)*CHELEM;

    // ---- stage S slice + chunk operands into smem ----
    #pragma unroll
    for (int it = 0; it < 8; it++) {
        int idx = tid + it*256;          // 0..2047 float4s
        int k = idx >> 3, vi = idx & 7;
        *(float4*)&Ss[k*36 + vi*4] = *(const float4*)&Sin[(long)k*DV + v0 + vi*4];
    }
    {
        const float4* wsrc = (const float4*)(g_wT + cb);
        const float4* qsrc = (const float4*)(g_qT + cb);
        const float4* ksrc = (const float4*)(g_kn + cb);
        #pragma unroll
        for (int it = 0; it < 8; it++) {
            int idx = tid + it*256;
            ((float4*)wT )[idx] = wsrc[idx];
            ((float4*)qT )[idx] = qsrc[idx];
            ((float4*)kns)[idx] = ksrc[idx];
        }
        const float* asrc = g_attnT + ((long)bh*NCH + t)*CC*CC;
        #pragma unroll
        for (int it = 0; it < 4; it++) {
            int idx = tid + it*256;
            aT[(idx>>5)*36 + (idx&31)] = asrc[idx];
        }
    }
    __syncthreads();

    // ---- fused u = w.S and o = q.S  (thread: rows c=4*wid..+3, col v=lane) ----
    float au0=0,au1=0,au2=0,au3=0, ao0=0,ao1=0,ao2=0,ao3=0;
    #pragma unroll 4
    for (int k = 0; k < 256; k++) {
        float s   = Ss[k*36 + lane];
        float4 w4 = *(float4*)&wT[k*32 + wid*4];   // broadcast within warp
        float4 q4 = *(float4*)&qT[k*32 + wid*4];   // broadcast
        au0 += w4.x*s; au1 += w4.y*s; au2 += w4.z*s; au3 += w4.w*s;
        ao0 += q4.x*s; ao1 += q4.y*s; ao2 += q4.z*s; ao3 += q4.w*s;
    }
    {
        const float* up = g_u + cb;
        int c = wid*4;
        us[(c+0)*36 + lane] = up[(c+0)*DV + v0 + lane] - au0;
        us[(c+1)*36 + lane] = up[(c+1)*DV + v0 + lane] - au1;
        us[(c+2)*36 + lane] = up[(c+2)*DV + v0 + lane] - au2;
        us[(c+3)*36 + lane] = up[(c+3)*DV + v0 + lane] - au3;
    }
    __syncthreads();

    // ---- o += attn_local . u ----
    #pragma unroll 4
    for (int d = 0; d < 32; d++) {
        float uu  = us[d*36 + lane];
        float4 a4 = *(float4*)&aT[d*36 + wid*4];   // broadcast; a4.e = attn[c=4wid+e][d]
        ao0 += a4.x*uu; ao1 += a4.y*uu; ao2 += a4.z*uu; ao3 += a4.w*uu;
    }
    {
        float* op = outp + ((long)bh*LSEQ + (long)t*CC)*DV;
        int c = wid*4;
        op[(c+0)*DV + v0 + lane] = ao0;
        op[(c+1)*DV + v0 + lane] = ao1;
        op[(c+2)*DV + v0 + lane] = ao2;
        op[(c+3)*DV + v0 + lane] = ao3;
    }

    // ---- S_new = gm*S + kn^T . u  (remap: lane = k offset, warp = v group of 4) ----
    const int kx = lane, vy = wid;
    float acc[32];
    #pragma unroll
    for (int z = 0; z < 32; z++) acc[z] = 0.f;
    #pragma unroll 2
    for (int c = 0; c < 32; c++) {
        float4 u4 = *(float4*)&us[c*36 + vy*4];    // broadcast
        const float* kr = &kns[c*DK + kx];
        #pragma unroll
        for (int kg = 0; kg < 8; kg++) {
            float kv = kr[kg*32];
            acc[kg*4+0] += kv*u4.x;
            acc[kg*4+1] += kv*u4.y;
            acc[kg*4+2] += kv*u4.z;
            acc[kg*4+3] += kv*u4.w;
        }
    }
    {
        float gm = g_gm[bh*NCH + t];
        #pragma unroll
        for (int kg = 0; kg < 8; kg++) {
            int k = kg*32 + kx;
            float4 so = *(float4*)&Ss[k*36 + vy*4];
            float4 sn = make_float4(gm*so.x + acc[kg*4+0],
                                    gm*so.y + acc[kg*4+1],
                                    gm*so.z + acc[kg*4+2],
                                    gm*so.w + acc[kg*4+3]);
            *(float4*)&Sout[(long)k*DV + v0 + vy*4] = sn;
            if (sFinal) *(float4*)&sFinal[(long)bh*DK*DV + (long)k*DV + v0 + vy*4] = sn;
        }
    }
}

// ================= launch =================
extern "C" void kernel_launch(void* const* d_in, const int* in_sizes, int n_in,
                              void* d_out, int out_size) {
    const float* q     = (const float*)d_in[0];
    const float* k     = (const float*)d_in[1];
    const float* v     = (const float*)d_in[2];
    const float* beta  = (const float*)d_in[3];
    const float* gamma = (const float*)d_in[4];
    float* outp = (float*)d_out;
    float* sfin = outp + (long)BHn*LSEQ*DV;   // S appended after out

    static int attr_done = 0;
    cudaFuncSetAttribute(pre_kernel,  cudaFuncAttributeMaxDynamicSharedMemorySize,
                         PRE_SMEM_FLOATS*4);
    cudaFuncSetAttribute(scan_kernel, cudaFuncAttributeMaxDynamicSharedMemorySize,
                         SCAN_SMEM_FLOATS*4);
    (void)attr_done; (void)in_sizes; (void)n_in; (void)out_size;

    zero_kernel<<<4096, 256>>>();
    pre_kernel<<<BHn*NCH, 256, PRE_SMEM_FLOATS*4>>>(q, k, v, beta, gamma);
    for (int t = 0; t < NCH; t++) {
        scan_kernel<<<dim3(8, BHn), 256, SCAN_SMEM_FLOATS*4>>>(
            t, outp, (t == NCH-1) ? sfin : nullptr);
    }
}